// round 14
// baseline (speedup 1.0000x reference)
#include <cuda_runtime.h>
#include <cuda_bf16.h>
#include <math.h>
#include <stdint.h>

// Problem constants
#define BB 4
#define NN 2048
#define DD 1024
#define HH 16
#define DH 64
#define BH (BB*HH)          // 64
#define M_ROWS (BB*NN)      // 8192

// Scratch (static device globals — allocation-free)
__device__ float g_q[BH * NN * DH];      // [b*H+h][n][dh]
__device__ float g_k[BH * NN * DH];      // [b*H+h][n][dh]
__device__ float g_vT[BH * DH * NN];     // [b*H+h][dh][n]  (transposed, gated)
__device__ float g_attn[M_ROWS * DD];    // [b*N+n][D]
__device__ float g_bias[NN];             // per-key additive logit bias
__device__ float g_gate[NN];             // per-key value gate

// ---------------------------------------------------------------------------
// m16n8k16 bf16 mma + ldmatrix (portable PTX, sm_80+/sm_75+)
// C frag: c0=(r,2q) c1=(r,2q+1) c2=(r+8,2q) c3=(r+8,2q+1), r=lane/4, q=lane%4
// ---------------------------------------------------------------------------
__device__ __forceinline__ void mma_bf16(float c[4], const uint32_t a[4],
                                         uint32_t b0, uint32_t b1)
{
    asm volatile(
        "mma.sync.aligned.m16n8k16.row.col.f32.bf16.bf16.f32 "
        "{%0,%1,%2,%3}, {%4,%5,%6,%7}, {%8,%9}, {%0,%1,%2,%3};"
        : "+f"(c[0]), "+f"(c[1]), "+f"(c[2]), "+f"(c[3])
        : "r"(a[0]), "r"(a[1]), "r"(a[2]), "r"(a[3]), "r"(b0), "r"(b1));
}

__device__ __forceinline__ void ldm_x4(uint32_t r[4], uint32_t addr)
{
    asm volatile("ldmatrix.sync.aligned.m8n8.x4.shared.b16 {%0,%1,%2,%3}, [%4];"
                 : "=r"(r[0]), "=r"(r[1]), "=r"(r[2]), "=r"(r[3]) : "r"(addr));
}

__device__ __forceinline__ uint32_t s2u(const void* p) {
    uint32_t a;
    asm("{ .reg .u64 t; cvta.to.shared.u64 t, %1; cvt.u32.u64 %0, t; }"
        : "=r"(a) : "l"(p));
    return a;
}

// Convert 8 consecutive fp32 -> bf16 hi/lo, store 16B each
__device__ __forceinline__ void cvt8(const float* __restrict__ src,
                                     __nv_bfloat16* dhi, __nv_bfloat16* dlo)
{
    float4 a = *(const float4*)src;
    float4 b = *(const float4*)(src + 4);
    float f[8] = {a.x, a.y, a.z, a.w, b.x, b.y, b.z, b.w};
    uint32_t h[4], l[4];
    #pragma unroll
    for (int i = 0; i < 4; i++) {
        float x = f[2*i], y = f[2*i+1];
        __nv_bfloat16 hx = __float2bfloat16_rn(x);
        __nv_bfloat16 hy = __float2bfloat16_rn(y);
        __nv_bfloat162 hp = __halves2bfloat162(hx, hy);
        h[i] = *reinterpret_cast<uint32_t*>(&hp);
        __nv_bfloat162 lp = __floats2bfloat162_rn(x - __bfloat162float(hx),
                                                  y - __bfloat162float(hy));
        l[i] = *reinterpret_cast<uint32_t*>(&lp);
    }
    *(uint4*)dhi = make_uint4(h[0], h[1], h[2], h[3]);
    *(uint4*)dlo = make_uint4(l[0], l[1], l[2], l[3]);
}

// Pack two fp32 -> bf16x2 hi and lo words
__device__ __forceinline__ void split2(float x, float y, uint32_t& hw, uint32_t& lw)
{
    __nv_bfloat16 hx = __float2bfloat16_rn(x);
    __nv_bfloat16 hy = __float2bfloat16_rn(y);
    __nv_bfloat162 hp = __halves2bfloat162(hx, hy);
    hw = *reinterpret_cast<uint32_t*>(&hp);
    __nv_bfloat162 lp = __floats2bfloat162_rn(x - __bfloat162float(hx),
                                              y - __bfloat162float(hy));
    lw = *reinterpret_cast<uint32_t*>(&lp);
}

// ---------------------------------------------------------------------------
// Prep: col_bias and gate per key position
// ---------------------------------------------------------------------------
__global__ void prep_kernel(const float* __restrict__ ctx_ppr,
                            const float* __restrict__ ctx_trust,
                            const float* __restrict__ log_ppr_alpha,
                            const float* __restrict__ trust_scale,
                            const int* __restrict__ n_ctx_p) {
    int i = blockIdx.x * blockDim.x + threadIdx.x;
    if (i >= NN) return;
    int nc = *n_ctx_p;
    float bias = 0.0f, gate = 1.0f;
    if (i < nc) {
        bias = -log_ppr_alpha[0] * logf(fmaxf(ctx_ppr[i], 1e-8f));
        gate = 1.0f / (1.0f + __expf(-trust_scale[0] * ctx_trust[i]));
    }
    g_bias[i] = bias;
    g_gate[i] = gate;
}

// ---------------------------------------------------------------------------
// Split-bf16 MMA GEMM core: C[128,128] = A[128rows,K=1024] * W[128rows,K]^T
// 256 threads, 8 warps (2m x 4n), warp tile 64x32. BK=32, double-buffered.
// SMEM stage (halves): Ah[128][40] | Al | Wh | Wl
// Fragment loads via ldmatrix.x4 (conflict-free at stride GS=40).
// ---------------------------------------------------------------------------
#define GS 40
#define GT (128*GS)            // 5120 halves per tile
#define GSTG (4*GT)            // 20480 halves per stage
#define GEMM_SMEM (2*GSTG*2)   // 81920 bytes

__device__ __forceinline__ void gemm_stage(const float* __restrict__ Ab,
                                           const float* __restrict__ Wb,
                                           int k0, __nv_bfloat16* st, int tid)
{
    #pragma unroll
    for (int i = 0; i < 2; i++) {
        int g = tid + 256 * i;          // 0..511
        int row = g >> 2, c8 = (g & 3) * 8;
        cvt8(Ab + (size_t)row * DD + k0 + c8,
             st + row * GS + c8, st + GT + row * GS + c8);
        cvt8(Wb + (size_t)row * DD + k0 + c8,
             st + 2*GT + row * GS + c8, st + 3*GT + row * GS + c8);
    }
}

__device__ __forceinline__ void gemm_core_mma(const float* __restrict__ Ab,
                                              const float* __restrict__ Wb,
                                              __nv_bfloat16* sm,
                                              float C[4][4][4])
{
    int tid = threadIdx.x;
    int warp = tid >> 5, lane = tid & 31;
    int wm = warp >> 2, wn = warp & 3;
    uint32_t sbase = s2u(sm);

    // ldmatrix lane addressing (in halves, converted to bytes at use)
    // A (16x16 tiles, row-major): lanes 0-15 rows, 16-31 rows w/ col block 8
    int a_off = (wm*64 + (lane & 15)) * GS + ((lane >> 4) << 3);
    // B (two adjacent 8-row n-tiles per x4)
    int b_off = (wn*32 + (lane & 7) + ((lane >> 3) & 1) * 8) * GS
              + ((lane >> 4) << 3);

    #pragma unroll
    for (int mi = 0; mi < 4; mi++)
        #pragma unroll
        for (int ni = 0; ni < 4; ni++)
            #pragma unroll
            for (int e = 0; e < 4; e++) C[mi][ni][e] = 0.0f;

    gemm_stage(Ab, Wb, 0, sm, tid);
    __syncthreads();

    for (int c = 0; c < 32; c++) {
        int s = c & 1;
        if (c + 1 < 32)
            gemm_stage(Ab, Wb, (c + 1) * 32, sm + (1 - s) * GSTG, tid);

        uint32_t sOff = (uint32_t)s * GSTG;
        #pragma unroll
        for (int ks = 0; ks < 2; ks++) {
            uint32_t ah[4][4], al[4][4];
            #pragma unroll
            for (int mi = 0; mi < 4; mi++) {
                uint32_t aa = sbase + 2u * (sOff + a_off + mi * 16 * GS + ks * 16);
                ldm_x4(ah[mi], aa);
                ldm_x4(al[mi], aa + 2u * GT);
            }
            #pragma unroll
            for (int p = 0; p < 2; p++) {
                uint32_t bb = sbase + 2u * (sOff + 2*GT + b_off + p * 16 * GS + ks * 16);
                uint32_t bh[4], bl[4];
                ldm_x4(bh, bb);
                ldm_x4(bl, bb + 2u * GT);
                #pragma unroll
                for (int mi = 0; mi < 4; mi++) {
                    mma_bf16(C[mi][2*p],   ah[mi], bh[0], bh[2]);
                    mma_bf16(C[mi][2*p],   ah[mi], bl[0], bl[2]);
                    mma_bf16(C[mi][2*p],   al[mi], bh[0], bh[2]);
                    mma_bf16(C[mi][2*p+1], ah[mi], bh[1], bh[3]);
                    mma_bf16(C[mi][2*p+1], ah[mi], bl[1], bl[3]);
                    mma_bf16(C[mi][2*p+1], al[mi], bh[1], bh[3]);
                }
            }
        }
        __syncthreads();
    }
}

// QKV GEMM: scatter into g_q/g_k (head-major) and g_vT (transposed, gated)
__global__ void __launch_bounds__(256, 2)
qkv_mma_kernel(const float* __restrict__ x,
               const float* __restrict__ W_in,
               const float* __restrict__ b_in) {
    extern __shared__ __nv_bfloat16 smg[];
    float C[4][4][4];
    const float* Ab = x + (size_t)blockIdx.y * 128 * DD;
    const float* Wb = W_in + (size_t)blockIdx.x * 128 * DD;
    gemm_core_mma(Ab, Wb, smg, C);

    int tid = threadIdx.x, warp = tid >> 5, lane = tid & 31;
    int r = lane >> 2, q = lane & 3;
    int wm = warp >> 2, wn = warp & 3;
    int brow = blockIdx.y * 128, bcol = blockIdx.x * 128;
    int which = bcol >> 10;     // 0=q 1=k 2=v (uniform per block)

    #pragma unroll
    for (int mi = 0; mi < 4; mi++) {
        #pragma unroll
        for (int e2 = 0; e2 < 2; e2++) {
            int grow = brow + wm * 64 + mi * 16 + r + e2 * 8;
            int b = grow >> 11, n = grow & (NN - 1);
            float gate = g_gate[n];
            #pragma unroll
            for (int ni = 0; ni < 4; ni++) {
                int gcol = bcol + wn * 32 + ni * 8 + 2 * q;
                float v0 = C[mi][ni][e2 * 2 + 0] + b_in[gcol];
                float v1 = C[mi][ni][e2 * 2 + 1] + b_in[gcol + 1];
                int e = gcol & (DD - 1);
                int h = e >> 6, dh = e & (DH - 1);
                if (which == 2) {
                    size_t base = ((size_t)(b * HH + h) * DH + dh) * NN + n;
                    g_vT[base] = v0 * gate;
                    g_vT[base + NN] = v1 * gate;
                } else {
                    float* dst = which ? g_k : g_q;
                    *(float2*)&dst[((size_t)(b * HH + h) * NN + n) * DH + dh] =
                        make_float2(v0, v1);
                }
            }
        }
    }
}

// Output projection GEMM
__global__ void __launch_bounds__(256, 2)
out_mma_kernel(const float* __restrict__ W_out,
               const float* __restrict__ b_out,
               float* __restrict__ out) {
    extern __shared__ __nv_bfloat16 smg[];
    float C[4][4][4];
    const float* Ab = g_attn + (size_t)blockIdx.y * 128 * DD;
    const float* Wb = W_out + (size_t)blockIdx.x * 128 * DD;
    gemm_core_mma(Ab, Wb, smg, C);

    int tid = threadIdx.x, warp = tid >> 5, lane = tid & 31;
    int r = lane >> 2, q = lane & 3;
    int wm = warp >> 2, wn = warp & 3;
    int brow = blockIdx.y * 128, bcol = blockIdx.x * 128;

    #pragma unroll
    for (int mi = 0; mi < 4; mi++) {
        #pragma unroll
        for (int e2 = 0; e2 < 2; e2++) {
            int grow = brow + wm * 64 + mi * 16 + r + e2 * 8;
            #pragma unroll
            for (int ni = 0; ni < 4; ni++) {
                int gcol = bcol + wn * 32 + ni * 8 + 2 * q;
                float v0 = C[mi][ni][e2 * 2 + 0] + b_out[gcol];
                float v1 = C[mi][ni][e2 * 2 + 1] + b_out[gcol + 1];
                *(float2*)&out[(size_t)grow * DD + gcol] = make_float2(v0, v1);
            }
        }
    }
}

// ---------------------------------------------------------------------------
// Flash attention with split-bf16 warp MMA + ldmatrix.
// CTA: 128 queries x one bh head; 8 warps, warp = 16 query rows.
// 32 chunks of 64 keys, K/V^T double-buffered.
// SMEM layout (halves, row stride 72):
//   QH[128][72] @0, QL @9216
//   KV stage s @18432+s*18432: KH[64][72]+0, KL+4608, VH(Vt)[64][72]+9216, VL+13824
//   bias: 2 x 64 floats @ byte 110592
// ---------------------------------------------------------------------------
#define AS 72
#define A_QL 9216
#define A_KV 18432
#define A_KVSTG 18432
#define ATTN_SMEM (110592 + 512)

__device__ __forceinline__ void attn_stage_kv(int bh, int kt, __nv_bfloat16* st,
                                              float* sbias, int tid)
{
    const float* Kg = g_k + ((size_t)bh * NN + kt * 64) * DH;
    const float* Vg = g_vT + (size_t)bh * DH * NN + kt * 64;
    #pragma unroll
    for (int i = 0; i < 2; i++) {
        int g = tid + 256 * i;          // 0..511
        int row = g >> 3, c8 = (g & 7) * 8;
        cvt8(Kg + (size_t)row * DH + c8,
             st + row * AS + c8, st + 4608 + row * AS + c8);
        cvt8(Vg + (size_t)row * NN + c8,
             st + 9216 + row * AS + c8, st + 13824 + row * AS + c8);
    }
    if (tid < 64) sbias[tid] = g_bias[kt * 64 + tid];
}

__global__ void __launch_bounds__(256, 2)
attn_mma_kernel() {
    extern __shared__ __nv_bfloat16 sma[];
    float* sbias = (float*)((char*)sma + 110592);
    uint32_t sbase = s2u(sma);
    int tid = threadIdx.x, warp = tid >> 5, lane = tid & 31;
    int r = lane >> 2, q = lane & 3;
    int bh = blockIdx.y;
    int q0 = blockIdx.x * 128;

    // ldmatrix lane addressing (halves)
    int qa_off = (warp*16 + (lane & 15)) * AS + ((lane >> 4) << 3);   // Q A-frag
    int kb_off = ((lane & 7) + ((lane >> 3) & 1) * 8) * AS
               + ((lane >> 4) << 3);                                  // K/V B-frag pairs

    // stage Q tile (128 x 64)
    const float* Qg = g_q + ((size_t)bh * NN + q0) * DH;
    #pragma unroll
    for (int i = 0; i < 4; i++) {
        int g = tid + 256 * i;          // 0..1023
        int row = g >> 3, c8 = (g & 7) * 8;
        cvt8(Qg + (size_t)row * DH + c8,
             sma + row * AS + c8, sma + A_QL + row * AS + c8);
    }
    attn_stage_kv(bh, 0, sma + A_KV, sbias, tid);
    __syncthreads();

    float O[8][4];
    #pragma unroll
    for (int ni = 0; ni < 8; ni++)
        #pragma unroll
        for (int e = 0; e < 4; e++) O[ni][e] = 0.0f;
    float m0 = -1e30f, m1 = -1e30f, l0 = 0.0f, l1 = 0.0f;
    const float scale = 0.125f;
    int qrow = warp * 16 + r;

    for (int kt = 0; kt < 32; kt++) {
        int s = kt & 1;
        if (kt + 1 < 32)
            attn_stage_kv(bh, kt + 1, sma + A_KV + (1 - s) * A_KVSTG,
                          sbias + (1 - s) * 64, tid);

        uint32_t kvOff = A_KV + (uint32_t)s * A_KVSTG;
        const float* bptr = sbias + s * 64;

        // ---- S = Q K^T (split-bf16) ----
        float S[8][4];
        #pragma unroll
        for (int ni = 0; ni < 8; ni++)
            #pragma unroll
            for (int e = 0; e < 4; e++) S[ni][e] = 0.0f;

        #pragma unroll
        for (int ks = 0; ks < 4; ks++) {
            uint32_t qa = sbase + 2u * (qa_off + ks * 16);
            uint32_t qh[4], ql[4];
            ldm_x4(qh, qa);
            ldm_x4(ql, qa + 2u * A_QL);
            #pragma unroll
            for (int p = 0; p < 4; p++) {
                uint32_t ka = sbase + 2u * (kvOff + kb_off + p * 16 * AS + ks * 16);
                uint32_t kh[4], kl[4];
                ldm_x4(kh, ka);
                ldm_x4(kl, ka + 2u * 4608);
                mma_bf16(S[2*p],   qh, kh[0], kh[2]);
                mma_bf16(S[2*p],   qh, kl[0], kl[2]);
                mma_bf16(S[2*p],   ql, kh[0], kh[2]);
                mma_bf16(S[2*p+1], qh, kh[1], kh[3]);
                mma_bf16(S[2*p+1], qh, kl[1], kl[3]);
                mma_bf16(S[2*p+1], ql, kh[1], kh[3]);
            }
        }

        // ---- scale + bias, row max ----
        float rmax0 = -1e30f, rmax1 = -1e30f;
        #pragma unroll
        for (int ni = 0; ni < 8; ni++) {
            float2 bb = *(const float2*)&bptr[ni * 8 + 2 * q];
            S[ni][0] = fmaf(S[ni][0], scale, bb.x);
            S[ni][1] = fmaf(S[ni][1], scale, bb.y);
            S[ni][2] = fmaf(S[ni][2], scale, bb.x);
            S[ni][3] = fmaf(S[ni][3], scale, bb.y);
            rmax0 = fmaxf(rmax0, fmaxf(S[ni][0], S[ni][1]));
            rmax1 = fmaxf(rmax1, fmaxf(S[ni][2], S[ni][3]));
        }
        rmax0 = fmaxf(rmax0, __shfl_xor_sync(0xFFFFFFFFu, rmax0, 1));
        rmax0 = fmaxf(rmax0, __shfl_xor_sync(0xFFFFFFFFu, rmax0, 2));
        rmax1 = fmaxf(rmax1, __shfl_xor_sync(0xFFFFFFFFu, rmax1, 1));
        rmax1 = fmaxf(rmax1, __shfl_xor_sync(0xFFFFFFFFu, rmax1, 2));

        float nm0 = fmaxf(m0, rmax0), nm1 = fmaxf(m1, rmax1);
        float corr0 = __expf(m0 - nm0), corr1 = __expf(m1 - nm1);
        m0 = nm0; m1 = nm1;

        float ls0 = 0.0f, ls1 = 0.0f;
        #pragma unroll
        for (int ni = 0; ni < 8; ni++) {
            S[ni][0] = __expf(S[ni][0] - nm0);
            S[ni][1] = __expf(S[ni][1] - nm0);
            S[ni][2] = __expf(S[ni][2] - nm1);
            S[ni][3] = __expf(S[ni][3] - nm1);
            ls0 += S[ni][0] + S[ni][1];
            ls1 += S[ni][2] + S[ni][3];
        }
        ls0 += __shfl_xor_sync(0xFFFFFFFFu, ls0, 1);
        ls0 += __shfl_xor_sync(0xFFFFFFFFu, ls0, 2);
        ls1 += __shfl_xor_sync(0xFFFFFFFFu, ls1, 1);
        ls1 += __shfl_xor_sync(0xFFFFFFFFu, ls1, 2);
        l0 = l0 * corr0 + ls0;
        l1 = l1 * corr1 + ls1;

        #pragma unroll
        for (int ni = 0; ni < 8; ni++) {
            O[ni][0] *= corr0; O[ni][1] *= corr0;
            O[ni][2] *= corr1; O[ni][3] *= corr1;
        }

        // ---- O += P V (P from registers: C-frag layout == A-frag layout) ----
        #pragma unroll
        for (int kk = 0; kk < 4; kk++) {
            const float* p0 = S[2 * kk];
            const float* p1 = S[2 * kk + 1];
            uint32_t ah[4], al[4];
            split2(p0[0], p0[1], ah[0], al[0]);
            split2(p0[2], p0[3], ah[1], al[1]);
            split2(p1[0], p1[1], ah[2], al[2]);
            split2(p1[2], p1[3], ah[3], al[3]);
            #pragma unroll
            for (int p = 0; p < 4; p++) {
                uint32_t va = sbase + 2u * (kvOff + 9216 + kb_off + p * 16 * AS + kk * 16);
                uint32_t vh[4], vl[4];
                ldm_x4(vh, va);
                ldm_x4(vl, va + 2u * 4608);
                mma_bf16(O[2*p],   ah, vh[0], vh[2]);
                mma_bf16(O[2*p],   ah, vl[0], vl[2]);
                mma_bf16(O[2*p],   al, vh[0], vh[2]);
                mma_bf16(O[2*p+1], ah, vh[1], vh[3]);
                mma_bf16(O[2*p+1], ah, vl[1], vl[3]);
                mma_bf16(O[2*p+1], al, vh[1], vh[3]);
            }
        }
        __syncthreads();
    }

    // ---- epilogue ----
    float inv0 = 1.0f / l0, inv1 = 1.0f / l1;
    int b = bh >> 4, h = bh & (HH - 1);
    int grow = q0 + qrow;
    #pragma unroll
    for (int nd = 0; nd < 8; nd++) {
        int col = h * DH + nd * 8 + 2 * q;
        *(float2*)&g_attn[((size_t)b * NN + grow) * DD + col] =
            make_float2(O[nd][0] * inv0, O[nd][1] * inv0);
        *(float2*)&g_attn[((size_t)b * NN + grow + 8) * DD + col] =
            make_float2(O[nd][2] * inv1, O[nd][3] * inv1);
    }
}

// ---------------------------------------------------------------------------
// Launch
// ---------------------------------------------------------------------------
extern "C" void kernel_launch(void* const* d_in, const int* in_sizes, int n_in,
                              void* d_out, int out_size) {
    const float* x           = (const float*)d_in[0];
    const int*   n_ctx       = (const int*)  d_in[1];
    const float* ctx_ppr     = (const float*)d_in[2];
    const float* ctx_trust   = (const float*)d_in[3];
    const float* W_in        = (const float*)d_in[4];
    const float* b_in        = (const float*)d_in[5];
    const float* W_out       = (const float*)d_in[6];
    const float* b_out       = (const float*)d_in[7];
    const float* log_alpha   = (const float*)d_in[8];
    const float* trust_scale = (const float*)d_in[9];
    float* out = (float*)d_out;

    cudaFuncSetAttribute(qkv_mma_kernel,
        cudaFuncAttributeMaxDynamicSharedMemorySize, GEMM_SMEM);
    cudaFuncSetAttribute(out_mma_kernel,
        cudaFuncAttributeMaxDynamicSharedMemorySize, GEMM_SMEM);
    cudaFuncSetAttribute(attn_mma_kernel,
        cudaFuncAttributeMaxDynamicSharedMemorySize, ATTN_SMEM);

    prep_kernel<<<2, 1024>>>(ctx_ppr, ctx_trust, log_alpha, trust_scale, n_ctx);

    dim3 g1(3 * DD / 128, M_ROWS / 128);   // 24 x 64
    qkv_mma_kernel<<<g1, 256, GEMM_SMEM>>>(x, W_in, b_in);

    dim3 ga(NN / 128, BH);                 // 16 x 64
    attn_mma_kernel<<<ga, 256, ATTN_SMEM>>>();

    dim3 g2(DD / 128, M_ROWS / 128);       // 8 x 64
    out_mma_kernel<<<g2, 256, GEMM_SMEM>>>(W_out, b_out, out);
}

// round 16
// speedup vs baseline: 1.1220x; 1.1220x over previous
#include <cuda_runtime.h>
#include <cuda_bf16.h>
#include <math.h>
#include <stdint.h>

// Problem constants
#define BB 4
#define NN 2048
#define DD 1024
#define HH 16
#define DH 64
#define BH (BB*HH)          // 64
#define M_ROWS (BB*NN)      // 8192

// Scratch (static device globals — allocation-free)
__device__ __nv_bfloat16 g_xh[M_ROWS * DD], g_xl[M_ROWS * DD];       // x split
__device__ __nv_bfloat16 g_wih[3 * DD * DD], g_wil[3 * DD * DD];     // W_in split
__device__ __nv_bfloat16 g_woh[DD * DD],     g_wol[DD * DD];         // W_out split
__device__ __nv_bfloat16 g_qh[BH * NN * DH], g_ql[BH * NN * DH];     // Q split
__device__ __nv_bfloat16 g_kh[BH * NN * DH], g_kl[BH * NN * DH];     // K split
__device__ __nv_bfloat16 g_vth[BH * DH * NN], g_vtl[BH * DH * NN];   // V^T split, gated
__device__ __nv_bfloat16 g_ah[M_ROWS * DD],  g_al[M_ROWS * DD];      // attn out split
__device__ float g_bias[NN];             // per-key additive logit bias
__device__ float g_gate[NN];             // per-key value gate

// ---------------------------------------------------------------------------
// PTX helpers (portable: mma sm_80+, cp.async sm_80+)
// ---------------------------------------------------------------------------
__device__ __forceinline__ void mma_bf16(float c[4], const uint32_t a[4],
                                         uint32_t b0, uint32_t b1)
{
    asm volatile(
        "mma.sync.aligned.m16n8k16.row.col.f32.bf16.bf16.f32 "
        "{%0,%1,%2,%3}, {%4,%5,%6,%7}, {%8,%9}, {%0,%1,%2,%3};"
        : "+f"(c[0]), "+f"(c[1]), "+f"(c[2]), "+f"(c[3])
        : "r"(a[0]), "r"(a[1]), "r"(a[2]), "r"(a[3]), "r"(b0), "r"(b1));
}

__device__ __forceinline__ uint32_t s2u(const void* p) {
    uint32_t a;
    asm("{ .reg .u64 t; cvta.to.shared.u64 t, %1; cvt.u32.u64 %0, t; }"
        : "=r"(a) : "l"(p));
    return a;
}

__device__ __forceinline__ void cpa16(uint32_t dst, const void* src) {
    asm volatile("cp.async.cg.shared.global [%0], [%1], 16;"
                 :: "r"(dst), "l"(src));
}
__device__ __forceinline__ void cp_commit() {
    asm volatile("cp.async.commit_group;");
}
template<int N> __device__ __forceinline__ void cp_wait() {
    asm volatile("cp.async.wait_group %0;" :: "n"(N));
}

// split fp32 -> bf16 hi + lo
__device__ __forceinline__ void split1(float x, __nv_bfloat16& h, __nv_bfloat16& l)
{
    h = __float2bfloat16_rn(x);
    l = __float2bfloat16_rn(x - __bfloat162float(h));
}
__device__ __forceinline__ void split2(float x, float y, uint32_t& hw, uint32_t& lw)
{
    __nv_bfloat16 hx = __float2bfloat16_rn(x);
    __nv_bfloat16 hy = __float2bfloat16_rn(y);
    __nv_bfloat162 hp = __halves2bfloat162(hx, hy);
    hw = *reinterpret_cast<uint32_t*>(&hp);
    __nv_bfloat162 lp = __floats2bfloat162_rn(x - __bfloat162float(hx),
                                              y - __bfloat162float(hy));
    lw = *reinterpret_cast<uint32_t*>(&lp);
}

// ---------------------------------------------------------------------------
// presplit: fp32 array -> bf16 hi/lo arrays (4 elems per thread)
// ---------------------------------------------------------------------------
__global__ void presplit_kernel(const float4* __restrict__ src,
                                uint2* __restrict__ dh,
                                uint2* __restrict__ dl, int n4)
{
    int i = blockIdx.x * blockDim.x + threadIdx.x;
    if (i >= n4) return;
    float4 v = src[i];
    uint32_t h0, l0, h1, l1;
    split2(v.x, v.y, h0, l0);
    split2(v.z, v.w, h1, l1);
    dh[i] = make_uint2(h0, h1);
    dl[i] = make_uint2(l0, l1);
}

// ---------------------------------------------------------------------------
// Prep: col_bias and gate per key position
// ---------------------------------------------------------------------------
__global__ void prep_kernel(const float* __restrict__ ctx_ppr,
                            const float* __restrict__ ctx_trust,
                            const float* __restrict__ log_ppr_alpha,
                            const float* __restrict__ trust_scale,
                            const int* __restrict__ n_ctx_p) {
    int i = blockIdx.x * blockDim.x + threadIdx.x;
    if (i >= NN) return;
    int nc = *n_ctx_p;
    float bias = 0.0f, gate = 1.0f;
    if (i < nc) {
        bias = -log_ppr_alpha[0] * logf(fmaxf(ctx_ppr[i], 1e-8f));
        gate = 1.0f / (1.0f + __expf(-trust_scale[0] * ctx_trust[i]));
    }
    g_bias[i] = bias;
    g_gate[i] = gate;
}

// ---------------------------------------------------------------------------
// Split-bf16 MMA GEMM core: C[128,128] = A[128rows,1024] * W[128rows,1024]^T
// 256 threads, 8 warps (2m x 4n), warp tile 64x32. BK=32, cp.async 2-stage.
// SMEM stage (halves, stride GS=40): Ah[128][40] | Al | Wh | Wl
// ---------------------------------------------------------------------------
#define GS 40
#define GT (128*GS)            // 5120 halves per tile
#define GSTG (4*GT)            // 20480 halves per stage
#define GEMM_SMEM (2*GSTG*2)   // 81920 bytes

__device__ __forceinline__ void gemm_stage_cp(const __nv_bfloat16* __restrict__ Ah,
                                              const __nv_bfloat16* __restrict__ Al,
                                              const __nv_bfloat16* __restrict__ Bh,
                                              const __nv_bfloat16* __restrict__ Bl,
                                              int k0, uint32_t stB, int tid)
{
    #pragma unroll
    for (int t = 0; t < 4; t++) {
        const __nv_bfloat16* base = (t == 0) ? Ah : (t == 1) ? Al
                                  : (t == 2) ? Bh : Bl;
        #pragma unroll
        for (int j = 0; j < 2; j++) {
            int idx = tid + 256 * j;          // 0..511
            int row = idx >> 2, ch = (idx & 3) * 8;
            cpa16(stB + 2u * (t * GT + row * GS + ch),
                  base + (size_t)row * DD + k0 + ch);
        }
    }
}

__device__ __forceinline__ void gemm_core_mma(const __nv_bfloat16* __restrict__ Ah,
                                              const __nv_bfloat16* __restrict__ Al,
                                              const __nv_bfloat16* __restrict__ Bh,
                                              const __nv_bfloat16* __restrict__ Bl,
                                              __nv_bfloat16* sm,
                                              float C[4][4][4])
{
    int tid = threadIdx.x;
    int warp = tid >> 5, lane = tid & 31;
    int r = lane >> 2, q = lane & 3;
    int wm = warp >> 2, wn = warp & 3;
    uint32_t sbase = s2u(sm);

    #pragma unroll
    for (int mi = 0; mi < 4; mi++)
        #pragma unroll
        for (int ni = 0; ni < 4; ni++)
            #pragma unroll
            for (int e = 0; e < 4; e++) C[mi][ni][e] = 0.0f;

    gemm_stage_cp(Ah, Al, Bh, Bl, 0, sbase, tid);
    cp_commit();

    for (int c = 0; c < 32; c++) {
        int s = c & 1;
        if (c + 1 < 32) {
            gemm_stage_cp(Ah, Al, Bh, Bl, (c + 1) * 32,
                          sbase + (uint32_t)(1 - s) * GSTG * 2, tid);
            cp_commit();
            cp_wait<1>();
        } else {
            cp_wait<0>();
        }
        __syncthreads();

        const __nv_bfloat16* sa = sm + s * GSTG;
        const __nv_bfloat16* sw = sa + 2 * GT;
        #pragma unroll
        for (int ks = 0; ks < 2; ks++) {
            int col = ks * 16 + 2 * q;
            uint32_t ah[4][4], al[4][4];
            #pragma unroll
            for (int mi = 0; mi < 4; mi++) {
                int row0 = wm * 64 + mi * 16 + r;
                const __nv_bfloat16* ph = sa + row0 * GS + col;
                const __nv_bfloat16* pl = ph + GT;
                ah[mi][0] = *(const uint32_t*)ph;
                ah[mi][1] = *(const uint32_t*)(ph + 8 * GS);
                ah[mi][2] = *(const uint32_t*)(ph + 8);
                ah[mi][3] = *(const uint32_t*)(ph + 8 * GS + 8);
                al[mi][0] = *(const uint32_t*)pl;
                al[mi][1] = *(const uint32_t*)(pl + 8 * GS);
                al[mi][2] = *(const uint32_t*)(pl + 8);
                al[mi][3] = *(const uint32_t*)(pl + 8 * GS + 8);
            }
            #pragma unroll
            for (int ni = 0; ni < 4; ni++) {
                int n0 = wn * 32 + ni * 8 + r;
                const __nv_bfloat16* pbh = sw + n0 * GS + col;
                const __nv_bfloat16* pbl = pbh + GT;
                uint32_t bh0 = *(const uint32_t*)pbh;
                uint32_t bh1 = *(const uint32_t*)(pbh + 8);
                uint32_t bl0 = *(const uint32_t*)pbl;
                uint32_t bl1 = *(const uint32_t*)(pbl + 8);
                #pragma unroll
                for (int mi = 0; mi < 4; mi++) {
                    mma_bf16(C[mi][ni], ah[mi], bh0, bh1);
                    mma_bf16(C[mi][ni], ah[mi], bl0, bl1);
                    mma_bf16(C[mi][ni], al[mi], bh0, bh1);
                }
            }
        }
        __syncthreads();
    }
}

// QKV GEMM: scatter split bf16 into g_q*/g_k* (head-major) and g_vt* (gated)
__global__ void __launch_bounds__(256, 2)
qkv_mma_kernel(const float* __restrict__ b_in) {
    extern __shared__ __nv_bfloat16 smg[];
    float C[4][4][4];
    const __nv_bfloat16* Ah = g_xh + (size_t)blockIdx.y * 128 * DD;
    const __nv_bfloat16* Al = g_xl + (size_t)blockIdx.y * 128 * DD;
    const __nv_bfloat16* Bh = g_wih + (size_t)blockIdx.x * 128 * DD;
    const __nv_bfloat16* Bl = g_wil + (size_t)blockIdx.x * 128 * DD;
    gemm_core_mma(Ah, Al, Bh, Bl, smg, C);

    int tid = threadIdx.x, warp = tid >> 5, lane = tid & 31;
    int r = lane >> 2, q = lane & 3;
    int wm = warp >> 2, wn = warp & 3;
    int brow = blockIdx.y * 128, bcol = blockIdx.x * 128;
    int which = bcol >> 10;     // 0=q 1=k 2=v (uniform per block)

    #pragma unroll
    for (int mi = 0; mi < 4; mi++) {
        #pragma unroll
        for (int e2 = 0; e2 < 2; e2++) {
            int grow = brow + wm * 64 + mi * 16 + r + e2 * 8;
            int b = grow >> 11, n = grow & (NN - 1);
            float gate = g_gate[n];
            #pragma unroll
            for (int ni = 0; ni < 4; ni++) {
                int gcol = bcol + wn * 32 + ni * 8 + 2 * q;
                float v0 = C[mi][ni][e2 * 2 + 0] + b_in[gcol];
                float v1 = C[mi][ni][e2 * 2 + 1] + b_in[gcol + 1];
                int e = gcol & (DD - 1);
                int h = e >> 6, dh = e & (DH - 1);
                if (which == 2) {
                    v0 *= gate; v1 *= gate;
                    size_t base = ((size_t)(b * HH + h) * DH + dh) * NN + n;
                    __nv_bfloat16 h0, l0, h1, l1;
                    split1(v0, h0, l0);
                    split1(v1, h1, l1);
                    g_vth[base] = h0;       g_vtl[base] = l0;
                    g_vth[base + NN] = h1;  g_vtl[base + NN] = l1;
                } else {
                    size_t idx = ((size_t)(b * HH + h) * NN + n) * DH + dh;
                    uint32_t hw, lw;
                    split2(v0, v1, hw, lw);
                    if (which == 0) {
                        *(uint32_t*)&g_qh[idx] = hw;
                        *(uint32_t*)&g_ql[idx] = lw;
                    } else {
                        *(uint32_t*)&g_kh[idx] = hw;
                        *(uint32_t*)&g_kl[idx] = lw;
                    }
                }
            }
        }
    }
}

// Output projection GEMM (reads pre-split attn output)
__global__ void __launch_bounds__(256, 2)
out_mma_kernel(const float* __restrict__ b_out,
               float* __restrict__ out) {
    extern __shared__ __nv_bfloat16 smg[];
    float C[4][4][4];
    const __nv_bfloat16* Ah = g_ah + (size_t)blockIdx.y * 128 * DD;
    const __nv_bfloat16* Al = g_al + (size_t)blockIdx.y * 128 * DD;
    const __nv_bfloat16* Bh = g_woh + (size_t)blockIdx.x * 128 * DD;
    const __nv_bfloat16* Bl = g_wol + (size_t)blockIdx.x * 128 * DD;
    gemm_core_mma(Ah, Al, Bh, Bl, smg, C);

    int tid = threadIdx.x, warp = tid >> 5, lane = tid & 31;
    int r = lane >> 2, q = lane & 3;
    int wm = warp >> 2, wn = warp & 3;
    int brow = blockIdx.y * 128, bcol = blockIdx.x * 128;

    #pragma unroll
    for (int mi = 0; mi < 4; mi++) {
        #pragma unroll
        for (int e2 = 0; e2 < 2; e2++) {
            int grow = brow + wm * 64 + mi * 16 + r + e2 * 8;
            #pragma unroll
            for (int ni = 0; ni < 4; ni++) {
                int gcol = bcol + wn * 32 + ni * 8 + 2 * q;
                float v0 = C[mi][ni][e2 * 2 + 0] + b_out[gcol];
                float v1 = C[mi][ni][e2 * 2 + 1] + b_out[gcol + 1];
                *(float2*)&out[(size_t)grow * DD + gcol] = make_float2(v0, v1);
            }
        }
    }
}

// ---------------------------------------------------------------------------
// Flash attention, split-bf16 warp MMA, cp.async staging (all inputs pre-split)
// CTA: 128 queries x one bh head; 8 warps, warp = 16 query rows.
// 32 chunks of 64 keys, double-buffered.
// SMEM (halves, row stride AS=72):
//   QH[128][72]@0, QL@9216
//   KV stage s @18432+s*18432: KH[64][72]+0, KL+4608, VH+9216, VL+13824
//   bias: 2 x 64 floats @ byte 110592
// ---------------------------------------------------------------------------
#define AS 72
#define A_QL 9216
#define A_KV 18432
#define A_KVSTG 18432
#define ATTN_SMEM (110592 + 512)

__device__ __forceinline__ void attn_stage_cp(int bh, int kt, uint32_t stB,
                                              float* sbias_dst, int tid)
{
    const __nv_bfloat16* Kh = g_kh + ((size_t)bh * NN + kt * 64) * DH;
    const __nv_bfloat16* Kl = g_kl + ((size_t)bh * NN + kt * 64) * DH;
    const __nv_bfloat16* Vh = g_vth + (size_t)bh * DH * NN + kt * 64;
    const __nv_bfloat16* Vl = g_vtl + (size_t)bh * DH * NN + kt * 64;
    #pragma unroll
    for (int t = 0; t < 4; t++) {
        const __nv_bfloat16* base = (t == 0) ? Kh : (t == 1) ? Kl
                                  : (t == 2) ? Vh : Vl;
        size_t stride = (t < 2) ? DH : NN;
        #pragma unroll
        for (int j = 0; j < 2; j++) {
            int idx = tid + 256 * j;          // 0..511
            int row = idx >> 3, ch = (idx & 7) * 8;
            cpa16(stB + 2u * (t * 4608 + row * AS + ch),
                  base + (size_t)row * stride + ch);
        }
    }
    if (tid < 64) sbias_dst[tid] = g_bias[kt * 64 + tid];
}

__global__ void __launch_bounds__(256, 2)
attn_mma_kernel() {
    extern __shared__ __nv_bfloat16 sma[];
    float* sbias = (float*)((char*)sma + 110592);
    uint32_t sbase = s2u(sma);
    int tid = threadIdx.x, warp = tid >> 5, lane = tid & 31;
    int r = lane >> 2, q = lane & 3;
    int bh = blockIdx.y;
    int q0 = blockIdx.x * 128;

    // stage Q tile (128 x 64, hi+lo) via cp.async
    {
        const __nv_bfloat16* Qh = g_qh + ((size_t)bh * NN + q0) * DH;
        const __nv_bfloat16* Ql = g_ql + ((size_t)bh * NN + q0) * DH;
        #pragma unroll
        for (int t = 0; t < 2; t++) {
            const __nv_bfloat16* base = t ? Ql : Qh;
            #pragma unroll
            for (int j = 0; j < 4; j++) {
                int idx = tid + 256 * j;      // 0..1023
                int row = idx >> 3, ch = (idx & 7) * 8;
                cpa16(sbase + 2u * (t * A_QL + row * AS + ch),
                      base + (size_t)row * DH + ch);
            }
        }
    }
    attn_stage_cp(bh, 0, sbase + 2u * A_KV, sbias, tid);
    cp_commit();

    float O[8][4];
    #pragma unroll
    for (int ni = 0; ni < 8; ni++)
        #pragma unroll
        for (int e = 0; e < 4; e++) O[ni][e] = 0.0f;
    float m0 = -1e30f, m1 = -1e30f, l0 = 0.0f, l1 = 0.0f;
    const float scale = 0.125f;
    int qrow = warp * 16 + r;

    for (int kt = 0; kt < 32; kt++) {
        int s = kt & 1;
        if (kt + 1 < 32) {
            attn_stage_cp(bh, kt + 1,
                          sbase + 2u * (A_KV + (uint32_t)(1 - s) * A_KVSTG),
                          sbias + (1 - s) * 64, tid);
            cp_commit();
            cp_wait<1>();
        } else {
            cp_wait<0>();
        }
        __syncthreads();

        const __nv_bfloat16* sk = sma + A_KV + s * A_KVSTG;
        const __nv_bfloat16* sv = sk + 9216;
        const float* bptr = sbias + s * 64;

        // ---- S = Q K^T (split-bf16) ----
        float S[8][4];
        #pragma unroll
        for (int ni = 0; ni < 8; ni++)
            #pragma unroll
            for (int e = 0; e < 4; e++) S[ni][e] = 0.0f;

        #pragma unroll
        for (int ks = 0; ks < 4; ks++) {
            int col = ks * 16 + 2 * q;
            const __nv_bfloat16* pq = sma + qrow * AS + col;
            const __nv_bfloat16* pql = pq + A_QL;
            uint32_t qh[4], ql[4];
            qh[0] = *(const uint32_t*)pq;
            qh[1] = *(const uint32_t*)(pq + 8 * AS);
            qh[2] = *(const uint32_t*)(pq + 8);
            qh[3] = *(const uint32_t*)(pq + 8 * AS + 8);
            ql[0] = *(const uint32_t*)pql;
            ql[1] = *(const uint32_t*)(pql + 8 * AS);
            ql[2] = *(const uint32_t*)(pql + 8);
            ql[3] = *(const uint32_t*)(pql + 8 * AS + 8);
            #pragma unroll
            for (int ni = 0; ni < 8; ni++) {
                int n0 = ni * 8 + r;
                const __nv_bfloat16* pk = sk + n0 * AS + col;
                const __nv_bfloat16* pkl = pk + 4608;
                uint32_t kh0 = *(const uint32_t*)pk;
                uint32_t kh1 = *(const uint32_t*)(pk + 8);
                uint32_t kl0 = *(const uint32_t*)pkl;
                uint32_t kl1 = *(const uint32_t*)(pkl + 8);
                mma_bf16(S[ni], qh, kh0, kh1);
                mma_bf16(S[ni], qh, kl0, kl1);
                mma_bf16(S[ni], ql, kh0, kh1);
            }
        }

        // ---- scale + bias, row max ----
        float rmax0 = -1e30f, rmax1 = -1e30f;
        #pragma unroll
        for (int ni = 0; ni < 8; ni++) {
            float2 bb = *(const float2*)&bptr[ni * 8 + 2 * q];
            S[ni][0] = fmaf(S[ni][0], scale, bb.x);
            S[ni][1] = fmaf(S[ni][1], scale, bb.y);
            S[ni][2] = fmaf(S[ni][2], scale, bb.x);
            S[ni][3] = fmaf(S[ni][3], scale, bb.y);
            rmax0 = fmaxf(rmax0, fmaxf(S[ni][0], S[ni][1]));
            rmax1 = fmaxf(rmax1, fmaxf(S[ni][2], S[ni][3]));
        }
        rmax0 = fmaxf(rmax0, __shfl_xor_sync(0xFFFFFFFFu, rmax0, 1));
        rmax0 = fmaxf(rmax0, __shfl_xor_sync(0xFFFFFFFFu, rmax0, 2));
        rmax1 = fmaxf(rmax1, __shfl_xor_sync(0xFFFFFFFFu, rmax1, 1));
        rmax1 = fmaxf(rmax1, __shfl_xor_sync(0xFFFFFFFFu, rmax1, 2));

        float nm0 = fmaxf(m0, rmax0), nm1 = fmaxf(m1, rmax1);
        float corr0 = __expf(m0 - nm0), corr1 = __expf(m1 - nm1);
        m0 = nm0; m1 = nm1;

        float ls0 = 0.0f, ls1 = 0.0f;
        #pragma unroll
        for (int ni = 0; ni < 8; ni++) {
            S[ni][0] = __expf(S[ni][0] - nm0);
            S[ni][1] = __expf(S[ni][1] - nm0);
            S[ni][2] = __expf(S[ni][2] - nm1);
            S[ni][3] = __expf(S[ni][3] - nm1);
            ls0 += S[ni][0] + S[ni][1];
            ls1 += S[ni][2] + S[ni][3];
        }
        ls0 += __shfl_xor_sync(0xFFFFFFFFu, ls0, 1);
        ls0 += __shfl_xor_sync(0xFFFFFFFFu, ls0, 2);
        ls1 += __shfl_xor_sync(0xFFFFFFFFu, ls1, 1);
        ls1 += __shfl_xor_sync(0xFFFFFFFFu, ls1, 2);
        l0 = l0 * corr0 + ls0;
        l1 = l1 * corr1 + ls1;

        #pragma unroll
        for (int ni = 0; ni < 8; ni++) {
            O[ni][0] *= corr0; O[ni][1] *= corr0;
            O[ni][2] *= corr1; O[ni][3] *= corr1;
        }

        // ---- O += P V (P from registers: C-frag layout == A-frag layout) ----
        #pragma unroll
        for (int kk = 0; kk < 4; kk++) {
            const float* p0 = S[2 * kk];
            const float* p1 = S[2 * kk + 1];
            uint32_t ah[4], al[4];
            split2(p0[0], p0[1], ah[0], al[0]);
            split2(p0[2], p0[3], ah[1], al[1]);
            split2(p1[0], p1[1], ah[2], al[2]);
            split2(p1[2], p1[3], ah[3], al[3]);
            int col = kk * 16 + 2 * q;
            #pragma unroll
            for (int nd = 0; nd < 8; nd++) {
                const __nv_bfloat16* pv = sv + (nd * 8 + r) * AS + col;
                uint32_t vh0 = *(const uint32_t*)pv;
                uint32_t vh1 = *(const uint32_t*)(pv + 8);
                uint32_t vl0 = *(const uint32_t*)(pv + 4608);
                uint32_t vl1 = *(const uint32_t*)(pv + 4608 + 8);
                mma_bf16(O[nd], ah, vh0, vh1);
                mma_bf16(O[nd], ah, vl0, vl1);
                mma_bf16(O[nd], al, vh0, vh1);
            }
        }
        __syncthreads();
    }

    // ---- epilogue: write pre-split attn output ----
    float inv0 = 1.0f / l0, inv1 = 1.0f / l1;
    int b = bh >> 4, h = bh & (HH - 1);
    int grow = q0 + qrow;
    #pragma unroll
    for (int nd = 0; nd < 8; nd++) {
        int col = h * DH + nd * 8 + 2 * q;
        uint32_t hw, lw;
        split2(O[nd][0] * inv0, O[nd][1] * inv0, hw, lw);
        *(uint32_t*)&g_ah[((size_t)b * NN + grow) * DD + col] = hw;
        *(uint32_t*)&g_al[((size_t)b * NN + grow) * DD + col] = lw;
        split2(O[nd][2] * inv1, O[nd][3] * inv1, hw, lw);
        *(uint32_t*)&g_ah[((size_t)b * NN + grow + 8) * DD + col] = hw;
        *(uint32_t*)&g_al[((size_t)b * NN + grow + 8) * DD + col] = lw;
    }
}

// ---------------------------------------------------------------------------
// Launch
// ---------------------------------------------------------------------------
extern "C" void kernel_launch(void* const* d_in, const int* in_sizes, int n_in,
                              void* d_out, int out_size) {
    const float* x           = (const float*)d_in[0];
    const int*   n_ctx       = (const int*)  d_in[1];
    const float* ctx_ppr     = (const float*)d_in[2];
    const float* ctx_trust   = (const float*)d_in[3];
    const float* W_in        = (const float*)d_in[4];
    const float* b_in        = (const float*)d_in[5];
    const float* W_out       = (const float*)d_in[6];
    const float* b_out       = (const float*)d_in[7];
    const float* log_alpha   = (const float*)d_in[8];
    const float* trust_scale = (const float*)d_in[9];
    float* out = (float*)d_out;

    cudaFuncSetAttribute(qkv_mma_kernel,
        cudaFuncAttributeMaxDynamicSharedMemorySize, GEMM_SMEM);
    cudaFuncSetAttribute(out_mma_kernel,
        cudaFuncAttributeMaxDynamicSharedMemorySize, GEMM_SMEM);
    cudaFuncSetAttribute(attn_mma_kernel,
        cudaFuncAttributeMaxDynamicSharedMemorySize, ATTN_SMEM);

    prep_kernel<<<2, 1024>>>(ctx_ppr, ctx_trust, log_alpha, trust_scale, n_ctx);

    // presplit x, W_in, W_out (resolve device-global addresses host-side is
    // not graph-friendly; use kernels with symbol refs directly)
    {
        __nv_bfloat16 *xh, *xl, *wih, *wil, *woh, *wol;
        cudaGetSymbolAddress((void**)&xh,  g_xh);
        cudaGetSymbolAddress((void**)&xl,  g_xl);
        cudaGetSymbolAddress((void**)&wih, g_wih);
        cudaGetSymbolAddress((void**)&wil, g_wil);
        cudaGetSymbolAddress((void**)&woh, g_woh);
        cudaGetSymbolAddress((void**)&wol, g_wol);
        presplit_kernel<<<M_ROWS * DD / 4 / 256, 256>>>(
            (const float4*)x, (uint2*)xh, (uint2*)xl, M_ROWS * DD / 4);
        presplit_kernel<<<3 * DD * DD / 4 / 256, 256>>>(
            (const float4*)W_in, (uint2*)wih, (uint2*)wil, 3 * DD * DD / 4);
        presplit_kernel<<<DD * DD / 4 / 256, 256>>>(
            (const float4*)W_out, (uint2*)woh, (uint2*)wol, DD * DD / 4);
    }

    dim3 g1(3 * DD / 128, M_ROWS / 128);   // 24 x 64
    qkv_mma_kernel<<<g1, 256, GEMM_SMEM>>>(b_in);

    dim3 ga(NN / 128, BH);                 // 16 x 64
    attn_mma_kernel<<<ga, 256, ATTN_SMEM>>>();

    dim3 g2(DD / 128, M_ROWS / 128);       // 8 x 64
    out_mma_kernel<<<g2, 256, GEMM_SMEM>>>(b_out, out);
}